// round 5
// baseline (speedup 1.0000x reference)
#include <cuda_runtime.h>
#include <math.h>
#include <cstdint>

#define BN 16
#define LL 1024
#define TOK (BN*LL)          // 16384 tokens
#define DM 256
#define DI 512
#define DS 16
#define DTR 16
#define NPROJ 48             // DTR + 2*DS

// ---------------- scratch (device globals; no allocation allowed) ------------
__device__ float g_h[TOK*DM];        // residual stream (b, l, m)
__device__ float g_xn[TOK*DM];       // layernormed
__device__ float g_xz[TOK*2*DI];     // in_proj output: [0:DI)=xin, [DI:2DI)=z
__device__ float g_u[TOK*DI];        // conv+silu output (u)
__device__ float g_proj[TOK*NPROJ];  // x_proj output: dt | B | C
__device__ float g_delta[TOK*DI];    // softplus(dt @ dtw + dtb)
__device__ float g_y[TOK*DI];        // scan output * silu(z)

// ---------------- helpers ----------------------------------------------------
__device__ __forceinline__ float sigmoidf_(float x) {
    return 1.f / (1.f + __expf(-x));
}
__device__ __forceinline__ float softplusf_(float x) {
    return (x > 20.f) ? x : log1pf(__expf(x));
}
__device__ __forceinline__ uint32_t smem_u32_(const void* p) {
    uint32_t a;
    asm("{ .reg .u64 t; cvta.to.shared.u64 t, %1; cvt.u32.u64 %0, t; }" : "=r"(a) : "l"(p));
    return a;
}
// pack two f32 -> bf16x2 (lo in lower half)
__device__ __forceinline__ uint32_t bf2_(float lo, float hi) {
    uint32_t r;
    asm("cvt.rn.bf16x2.f32 %0, %1, %2;" : "=r"(r) : "f"(hi), "f"(lo));
    return r;
}
#define LDSM4_(r0,r1,r2,r3,addr) \
    asm volatile("ldmatrix.sync.aligned.m8n8.x4.shared.b16 {%0,%1,%2,%3}, [%4];" \
        : "=r"(r0),"=r"(r1),"=r"(r2),"=r"(r3) : "r"(addr))
__device__ __forceinline__ void mma_bf16_(float* c, const uint32_t* a, const uint32_t* b) {
    asm volatile(
        "mma.sync.aligned.m16n8k16.row.col.f32.bf16.bf16.f32 "
        "{%0,%1,%2,%3}, {%4,%5,%6,%7}, {%8,%9}, {%0,%1,%2,%3};"
        : "+f"(c[0]), "+f"(c[1]), "+f"(c[2]), "+f"(c[3])
        : "r"(a[0]), "r"(a[1]), "r"(a[2]), "r"(a[3]), "r"(b[0]), "r"(b[1]));
}

// ---------------- bf16 tensor-core GEMM: C[M,N] = A[M,K] @ W[N,K]^T ----------
// CTA tile 128x128, BK=32, double-buffered SMEM, pitch-80B rows (LDSM
// conflict-free: 5 coprime 8). Warp tile 64x32. EPI 0: C=acc ; EPI 2: C+=acc.
#define GBM 128
#define GBN 128
#define GBK 32
#define PITCH 80u                        // bytes per 32-halves row
#define TILE_B (128u*PITCH)              // 10240 B
#define STAGE_B (2u*TILE_B)              // A + W
#define GEMM_SMEM (2u*STAGE_B)           // 40960 B

// byte offset of element (row, k) inside a tile
__device__ __forceinline__ uint32_t tofs_(int row, int k) {
    return (uint32_t)row * PITCH + (uint32_t)(k >> 3) * 16u + (uint32_t)(k & 7) * 2u;
}

// load one 128x32 f32 sub-tile -> bf16 regs (4 rows x 4 cols per thread)
__device__ __forceinline__ void tile_ldg_bf_(const float* __restrict__ G, int ld,
                                             int row0, int rmax, int k0, int tid,
                                             uint2* r) {
    #pragma unroll
    for (int i = 0; i < 4; i++) {
        int row = row0 + i * 32 + (tid >> 3);
        if (row > rmax) row = rmax;
        int c4 = tid & 7;
        float4 v = *reinterpret_cast<const float4*>(G + (size_t)row * ld + k0 + c4 * 4);
        r[i].x = bf2_(v.x, v.y);
        r[i].y = bf2_(v.z, v.w);
    }
}
__device__ __forceinline__ void tile_sts_bf_(const uint2* r, char* S, int tid) {
    #pragma unroll
    for (int i = 0; i < 4; i++) {
        int row = i * 32 + (tid >> 3);
        int c4 = tid & 7;
        uint32_t off = (uint32_t)row * PITCH + (uint32_t)(c4 >> 1) * 16u + (uint32_t)(c4 & 1) * 8u;
        *reinterpret_cast<uint2*>(S + off) = r[i];
    }
}

template<int EPI>
__global__ __launch_bounds__(256) void mma_gemm_kernel(
        const float* __restrict__ A, int lda,
        const float* __restrict__ W,
        float* __restrict__ C, int ldc,
        int K, int NW) {
    extern __shared__ char smem[];
    uint32_t sbase = smem_u32_(smem);
    int tid = threadIdx.x;
    int wid = tid >> 5, lane = tid & 31;
    int g = lane >> 2, tg = lane & 3;
    int bm = blockIdx.y * GBM;
    int bn = blockIdx.x * GBN;
    int wm0 = (wid & 1) * 64;
    int wn0 = (wid >> 1) * 32;

    // ldmatrix lane address components
    int rr = (lane & 7) + ((lane >> 3) & 1) * 8;   // row within 16
    int cc = (lane >> 4);                          // k-chunk select

    float acc[4][4][4];
    #pragma unroll
    for (int mf = 0; mf < 4; mf++)
        #pragma unroll
        for (int nf = 0; nf < 4; nf++)
            #pragma unroll
            for (int r = 0; r < 4; r++) acc[mf][nf][r] = 0.f;

    const int nst = K / GBK;

    {   // prologue: stage 0
        uint2 ra[4], rw[4];
        tile_ldg_bf_(A, lda, bm, TOK - 1, 0, tid, ra);
        tile_ldg_bf_(W, K,   bn, NW - 1,  0, tid, rw);
        tile_sts_bf_(ra, smem, tid);
        tile_sts_bf_(rw, smem + TILE_B, tid);
    }
    __syncthreads();

    for (int s = 0; s < nst; s++) {
        uint2 ra[4], rw[4];
        if (s + 1 < nst) {
            int k0 = (s + 1) * GBK;
            tile_ldg_bf_(A, lda, bm, TOK - 1, k0, tid, ra);
            tile_ldg_bf_(W, K,   bn, NW - 1,  k0, tid, rw);
        }
        uint32_t Sa = sbase + (uint32_t)(s & 1) * STAGE_B;
        uint32_t Sw = Sa + TILE_B;

        #pragma unroll
        for (int kk = 0; kk < 2; kk++) {
            uint32_t chunk_off = (uint32_t)(kk * 2 + cc) * 16u;
            uint32_t afr[4][4], bfr[4][2];
            #pragma unroll
            for (int mf = 0; mf < 4; mf++) {
                uint32_t ad = Sa + (uint32_t)(wm0 + mf * 16 + rr) * PITCH + chunk_off;
                LDSM4_(afr[mf][0], afr[mf][1], afr[mf][2], afr[mf][3], ad);
            }
            #pragma unroll
            for (int nh = 0; nh < 2; nh++) {
                uint32_t bd = Sw + (uint32_t)(wn0 + nh * 16 + rr) * PITCH + chunk_off;
                LDSM4_(bfr[2*nh][0], bfr[2*nh+1][0], bfr[2*nh][1], bfr[2*nh+1][1], bd);
            }
            #pragma unroll
            for (int mf = 0; mf < 4; mf++)
                #pragma unroll
                for (int nf = 0; nf < 4; nf++)
                    mma_bf16_(acc[mf][nf], afr[mf], bfr[nf]);
        }

        if (s + 1 < nst) {
            char* nb = smem + ((s + 1) & 1) * STAGE_B;
            tile_sts_bf_(ra, nb, tid);
            tile_sts_bf_(rw, nb + TILE_B, tid);
        }
        __syncthreads();
    }

    // epilogue: c0,c1 @(g, 2tg), c2,c3 @(g+8, 2tg)
    #pragma unroll
    for (int mf = 0; mf < 4; mf++) {
        int gr = bm + wm0 + mf * 16 + g;
        #pragma unroll
        for (int nf = 0; nf < 4; nf++) {
            int gc = bn + wn0 + nf * 8 + 2 * tg;
            if (gc >= NW) continue;
            float2 v01 = make_float2(acc[mf][nf][0], acc[mf][nf][1]);
            float2 v23 = make_float2(acc[mf][nf][2], acc[mf][nf][3]);
            float* p0 = C + (size_t)gr * ldc + gc;
            float* p1 = C + (size_t)(gr + 8) * ldc + gc;
            if (EPI == 2) {
                float2 o0 = *reinterpret_cast<float2*>(p0);
                float2 o1 = *reinterpret_cast<float2*>(p1);
                v01.x += o0.x; v01.y += o0.y;
                v23.x += o1.x; v23.y += o1.y;
            }
            *reinterpret_cast<float2*>(p0) = v01;
            *reinterpret_cast<float2*>(p1) = v23;
        }
    }
}

// ---------------- stem conv (k=3, pad=1) + relu ------------------------------
__global__ void stem_kernel(const float* __restrict__ x,
                            const float* __restrict__ sw,
                            const float* __restrict__ sb) {
    int t = blockIdx.x;
    int m = threadIdx.x;
    int b = t / LL, l = t % LL;
    __shared__ float xs[3][3];
    if (m < 9) {
        int c = m / 3, k = m % 3;
        int ll = l - 1 + k;
        xs[c][k] = (ll >= 0 && ll < LL) ? x[(b*3 + c)*LL + ll] : 0.f;
    }
    __syncthreads();
    float acc = sb[m];
    #pragma unroll
    for (int c = 0; c < 3; c++)
        #pragma unroll
        for (int k = 0; k < 3; k++)
            acc = fmaf(xs[c][k], sw[(m*3 + c)*3 + k], acc);
    g_h[t*DM + m] = fmaxf(acc, 0.f);
}

// ---------------- layernorm, warp-per-token (DM=256, 8 elems/lane) -----------
__device__ __forceinline__ float warp_sum_(float v) {
    #pragma unroll
    for (int o = 16; o; o >>= 1) v += __shfl_xor_sync(0xffffffffu, v, o);
    return v;
}
__global__ __launch_bounds__(256) void ln_kernel(const float* __restrict__ in,
                                                 const float* __restrict__ g,
                                                 const float* __restrict__ b,
                                                 float* __restrict__ out) {
    int wid = threadIdx.x >> 5, lane = threadIdx.x & 31;
    int t = blockIdx.x * 8 + wid;
    const float* row = in + (size_t)t * DM + lane * 8;
    float4 v0 = *reinterpret_cast<const float4*>(row);
    float4 v1 = *reinterpret_cast<const float4*>(row + 4);
    float s = v0.x+v0.y+v0.z+v0.w + v1.x+v1.y+v1.z+v1.w;
    float mean = warp_sum_(s) * (1.f / DM);
    float d0 = v0.x-mean, d1 = v0.y-mean, d2 = v0.z-mean, d3 = v0.w-mean;
    float d4 = v1.x-mean, d5 = v1.y-mean, d6 = v1.z-mean, d7 = v1.w-mean;
    float q = d0*d0+d1*d1+d2*d2+d3*d3+d4*d4+d5*d5+d6*d6+d7*d7;
    float rstd = rsqrtf(warp_sum_(q) * (1.f / DM) + 1e-5f);
    float4 g0 = *reinterpret_cast<const float4*>(g + lane * 8);
    float4 g1 = *reinterpret_cast<const float4*>(g + lane * 8 + 4);
    float4 b0 = *reinterpret_cast<const float4*>(b + lane * 8);
    float4 b1 = *reinterpret_cast<const float4*>(b + lane * 8 + 4);
    float* orow = out + (size_t)t * DM + lane * 8;
    float4 o0, o1;
    o0.x = d0*rstd*g0.x + b0.x; o0.y = d1*rstd*g0.y + b0.y;
    o0.z = d2*rstd*g0.z + b0.z; o0.w = d3*rstd*g0.w + b0.w;
    o1.x = d4*rstd*g1.x + b1.x; o1.y = d5*rstd*g1.y + b1.y;
    o1.z = d6*rstd*g1.z + b1.z; o1.w = d7*rstd*g1.w + b1.w;
    *reinterpret_cast<float4*>(orow) = o0;
    *reinterpret_cast<float4*>(orow + 4) = o1;
}

// ---------------- SIMT SGEMM (delta only): C = softplus(A @ W^T + bias) ------
#define TM 128
#define TN 128
#define TK 8
__global__ __launch_bounds__(256) void sgemm_sp_kernel(
        const float* __restrict__ A, int lda,
        const float* __restrict__ W,
        float* __restrict__ C, int ldc,
        const float* __restrict__ bias,
        int M, int N, int K) {
    __shared__ float As[TK][TM];
    __shared__ float Ws[TK][TN];
    int bm = blockIdx.y * TM;
    int bn = blockIdx.x * TN;
    int tid = threadIdx.x;
    int tr = tid / 16, tc = tid % 16;

    float acc[8][8];
    #pragma unroll
    for (int i = 0; i < 8; i++)
        #pragma unroll
        for (int j = 0; j < 8; j++) acc[i][j] = 0.f;

    for (int k0 = 0; k0 < K; k0 += TK) {
        {
            int row = tid >> 1, seg = (tid & 1) * 4;
            float4 v = *reinterpret_cast<const float4*>(A + (size_t)(bm+row)*lda + k0 + seg);
            As[seg+0][row] = v.x; As[seg+1][row] = v.y;
            As[seg+2][row] = v.z; As[seg+3][row] = v.w;
        }
        {
            int row = tid >> 1, seg = (tid & 1) * 4;
            float4 v = *reinterpret_cast<const float4*>(W + (size_t)(bn+row)*K + k0 + seg);
            Ws[seg+0][row] = v.x; Ws[seg+1][row] = v.y;
            Ws[seg+2][row] = v.z; Ws[seg+3][row] = v.w;
        }
        __syncthreads();
        #pragma unroll
        for (int kk = 0; kk < TK; kk++) {
            float a[8], bfr[8];
            *reinterpret_cast<float4*>(&a[0])   = *reinterpret_cast<float4*>(&As[kk][tr*8]);
            *reinterpret_cast<float4*>(&a[4])   = *reinterpret_cast<float4*>(&As[kk][tr*8+4]);
            *reinterpret_cast<float4*>(&bfr[0]) = *reinterpret_cast<float4*>(&Ws[kk][tc*8]);
            *reinterpret_cast<float4*>(&bfr[4]) = *reinterpret_cast<float4*>(&Ws[kk][tc*8+4]);
            #pragma unroll
            for (int i = 0; i < 8; i++)
                #pragma unroll
                for (int j = 0; j < 8; j++)
                    acc[i][j] = fmaf(a[i], bfr[j], acc[i][j]);
        }
        __syncthreads();
    }

    #pragma unroll
    for (int i = 0; i < 8; i++) {
        int gm = bm + tr*8 + i;
        #pragma unroll
        for (int j = 0; j < 8; j++) {
            int gn = bn + tc*8 + j;
            C[(size_t)gm*ldc + gn] = softplusf_(acc[i][j] + bias[gn]);
        }
    }
}

// ---------------- streaming causal depthwise conv (k=4) + silu ---------------
// grid (DI/64, BN), 64 threads; register window over l.
__global__ __launch_bounds__(64) void conv_silu_kernel(const float* __restrict__ cw,
                                                       const float* __restrict__ cb) {
    int d = blockIdx.x * 64 + threadIdx.x;
    int b = blockIdx.y;
    float w0 = cw[d*4+0], w1 = cw[d*4+1], w2 = cw[d*4+2], w3 = cw[d*4+3];
    float bias = cb[d];
    float x0 = 0.f, x1 = 0.f, x2 = 0.f;
    const float* src = g_xz + (size_t)b * LL * (2*DI) + d;
    float* dst = g_u + (size_t)b * LL * DI + d;
    #pragma unroll 4
    for (int l = 0; l < LL; l++) {
        float xl = src[(size_t)l * (2*DI)];
        float acc = bias + w0*x0 + w1*x1 + w2*x2 + w3*xl;
        dst[(size_t)l * DI] = acc * sigmoidf_(acc);
        x0 = x1; x1 = x2; x2 = xl;
    }
}

// ---------------- selective scan (sequential over L) + gate ------------------
// grid (DI/64, BN), 64 threads. Fast path when A[s] == -(s+1) (arange A_log):
// exp(dlt*A[s]) = q^(s+1), q = expf(-dlt)  -> 1 MUFU/step instead of 16.
#define SCH 8
__global__ __launch_bounds__(64) void scan_kernel(const float* __restrict__ Alog,
                                                  const float* __restrict__ Dp) {
    int b = blockIdx.y;
    int d = blockIdx.x * 64 + threadIdx.x;
    int tid = threadIdx.x;

    float A[DS], h[DS];
    bool fast = true;
    #pragma unroll
    for (int s = 0; s < DS; s++) {
        A[s] = -__expf(Alog[d*DS + s]);
        h[s] = 0.f;
        fast = fast && (fabsf(A[s] + (float)(s + 1)) < 1e-3f);
    }
    float Dd = Dp[d];

    __shared__ float sB[SCH][DS];
    __shared__ float sC[SCH][DS];
    int t0 = b * LL;

    for (int l0 = 0; l0 < LL; l0 += SCH) {
        #pragma unroll
        for (int r = 0; r < 4; r++) {
            int i = tid + r*64;
            int step = i >> 5;
            int j = i & 31;
            float val = g_proj[(size_t)(t0 + l0 + step)*NPROJ + DTR + j];
            if (j < DS) sB[step][j] = val;
            else        sC[step][j - DS] = val;
        }
        __syncthreads();

        float dc[SCH], uc[SCH], zc[SCH];
        #pragma unroll
        for (int i = 0; i < SCH; i++) {
            size_t t = (size_t)(t0 + l0 + i);
            dc[i] = g_delta[t*DI + d];
            uc[i] = g_u[t*DI + d];
            zc[i] = g_xz[t*2*DI + DI + d];
        }
        if (fast) {
            #pragma unroll
            for (int i = 0; i < SCH; i++) {
                float dlt = dc[i], uu = uc[i];
                float du = dlt * uu;
                float q  = __expf(-dlt);
                float q2 = q*q, q4 = q2*q2, q8 = q4*q4;
                float ep[DS];
                ep[0]=q;        ep[1]=q2;       ep[2]=q2*q;     ep[3]=q4;
                ep[4]=q4*q;     ep[5]=q4*q2;    ep[6]=ep[5]*q;  ep[7]=q8;
                ep[8]=q8*q;     ep[9]=q8*q2;    ep[10]=ep[9]*q; ep[11]=q8*q4;
                ep[12]=ep[11]*q; ep[13]=ep[11]*q2; ep[14]=ep[13]*q; ep[15]=q8*q8;
                float y = 0.f;
                #pragma unroll
                for (int s = 0; s < DS; s++) {
                    h[s] = fmaf(h[s], ep[s], du * sB[i][s]);
                    y = fmaf(h[s], sC[i][s], y);
                }
                y = fmaf(uu, Dd, y);
                float zz = zc[i];
                y *= zz * sigmoidf_(zz);
                g_y[(size_t)(t0 + l0 + i)*DI + d] = y;
            }
        } else {
            #pragma unroll
            for (int i = 0; i < SCH; i++) {
                float dlt = dc[i], uu = uc[i];
                float du = dlt * uu;
                float y = 0.f;
                #pragma unroll
                for (int s = 0; s < DS; s++) {
                    float ep = __expf(dlt * A[s]);
                    h[s] = fmaf(h[s], ep, du * sB[i][s]);
                    y = fmaf(h[s], sC[i][s], y);
                }
                y = fmaf(uu, Dd, y);
                float zz = zc[i];
                y *= zz * sigmoidf_(zz);
                g_y[(size_t)(t0 + l0 + i)*DI + d] = y;
            }
        }
        __syncthreads();
    }
}

// ---------------- final LN + head projection + sigmoid (warp/token) ----------
__global__ __launch_bounds__(256) void head_kernel(const float* __restrict__ g,
                                                   const float* __restrict__ b,
                                                   const float* __restrict__ hw,
                                                   const float* __restrict__ hb,
                                                   float* __restrict__ out) {
    int wid = threadIdx.x >> 5, lane = threadIdx.x & 31;
    int t = blockIdx.x * 8 + wid;
    const float* row = g_h + (size_t)t * DM + lane * 8;
    float4 v0 = *reinterpret_cast<const float4*>(row);
    float4 v1 = *reinterpret_cast<const float4*>(row + 4);
    float s = v0.x+v0.y+v0.z+v0.w + v1.x+v1.y+v1.z+v1.w;
    float mean = warp_sum_(s) * (1.f / DM);
    float d0 = v0.x-mean, d1 = v0.y-mean, d2 = v0.z-mean, d3 = v0.w-mean;
    float d4 = v1.x-mean, d5 = v1.y-mean, d6 = v1.z-mean, d7 = v1.w-mean;
    float q = d0*d0+d1*d1+d2*d2+d3*d3+d4*d4+d5*d5+d6*d6+d7*d7;
    float rstd = rsqrtf(warp_sum_(q) * (1.f / DM) + 1e-5f);
    float4 g0 = *reinterpret_cast<const float4*>(g + lane * 8);
    float4 g1 = *reinterpret_cast<const float4*>(g + lane * 8 + 4);
    float4 b0 = *reinterpret_cast<const float4*>(b + lane * 8);
    float4 b1 = *reinterpret_cast<const float4*>(b + lane * 8 + 4);
    float4 w0 = *reinterpret_cast<const float4*>(hw + lane * 8);
    float4 w1 = *reinterpret_cast<const float4*>(hw + lane * 8 + 4);
    float dot =
        (d0*rstd*g0.x + b0.x)*w0.x + (d1*rstd*g0.y + b0.y)*w0.y +
        (d2*rstd*g0.z + b0.z)*w0.z + (d3*rstd*g0.w + b0.w)*w0.w +
        (d4*rstd*g1.x + b1.x)*w1.x + (d5*rstd*g1.y + b1.y)*w1.y +
        (d6*rstd*g1.z + b1.z)*w1.z + (d7*rstd*g1.w + b1.w)*w1.w;
    float tot = warp_sum_(dot);
    if (lane == 0) out[t] = sigmoidf_(tot + hb[0]);
}

// ---------------- host launcher ----------------------------------------------
extern "C" void kernel_launch(void* const* d_in, const int* in_sizes, int n_in,
                              void* d_out, int out_size) {
    const float* x       = (const float*)d_in[0];
    const float* stem_w  = (const float*)d_in[1];
    const float* stem_b  = (const float*)d_in[2];
    const float* norm_g  = (const float*)d_in[3];
    const float* norm_b  = (const float*)d_in[4];
    const float* in_w    = (const float*)d_in[5];
    const float* conv_w  = (const float*)d_in[6];
    const float* conv_b  = (const float*)d_in[7];
    const float* xpw     = (const float*)d_in[8];
    const float* dtw     = (const float*)d_in[9];
    const float* dtb     = (const float*)d_in[10];
    const float* A_log   = (const float*)d_in[11];
    const float* Dp      = (const float*)d_in[12];
    const float* out_w   = (const float*)d_in[13];
    const float* fn_g    = (const float*)d_in[14];
    const float* fn_b    = (const float*)d_in[15];
    const float* head_w  = (const float*)d_in[16];
    const float* head_b  = (const float*)d_in[17];
    float* out = (float*)d_out;

    float *p_h, *p_xn, *p_xz, *p_u, *p_proj, *p_delta, *p_y;
    cudaGetSymbolAddress((void**)&p_h,     g_h);
    cudaGetSymbolAddress((void**)&p_xn,    g_xn);
    cudaGetSymbolAddress((void**)&p_xz,    g_xz);
    cudaGetSymbolAddress((void**)&p_u,     g_u);
    cudaGetSymbolAddress((void**)&p_proj,  g_proj);
    cudaGetSymbolAddress((void**)&p_delta, g_delta);
    cudaGetSymbolAddress((void**)&p_y,     g_y);

    cudaFuncSetAttribute(mma_gemm_kernel<0>,
                         cudaFuncAttributeMaxDynamicSharedMemorySize, GEMM_SMEM);
    cudaFuncSetAttribute(mma_gemm_kernel<2>,
                         cudaFuncAttributeMaxDynamicSharedMemorySize, GEMM_SMEM);

    stem_kernel<<<TOK, 256>>>(x, stem_w, stem_b);

    for (int i = 0; i < 4; i++) {
        ln_kernel<<<TOK/8, 256>>>(p_h, norm_g + i*DM, norm_b + i*DM, p_xn);

        // in_proj (bf16 mma): [TOK,1024] = xn[TOK,256] @ W[1024,256]^T
        {
            dim3 grid((2*DI)/GBN, TOK/GBM);
            mma_gemm_kernel<0><<<grid, 256, GEMM_SMEM>>>(
                p_xn, DM, in_w + (size_t)i*2*DI*DM, p_xz, 2*DI, DM, 2*DI);
        }

        conv_silu_kernel<<<dim3(DI/64, BN), 64>>>(conv_w + (size_t)i*DI*4,
                                                  conv_b + (size_t)i*DI);

        // x_proj (bf16 mma, N=48 padded to tile): [TOK,48] = u @ xw^T
        {
            dim3 grid(1, TOK/GBM);
            mma_gemm_kernel<0><<<grid, 256, GEMM_SMEM>>>(
                p_u, DI, xpw + (size_t)i*NPROJ*DI, p_proj, NPROJ, DI, NPROJ);
        }

        // delta (SIMT): softplus(dt[TOK,16] @ dtw[512,16]^T + dtb)
        {
            dim3 grid(DI/TN, TOK/TM);
            sgemm_sp_kernel<<<grid, 256>>>(p_proj, NPROJ, dtw + (size_t)i*DI*DTR,
                                           p_delta, DI, dtb + (size_t)i*DI,
                                           TOK, DI, DTR);
        }

        // scan + gate
        scan_kernel<<<dim3(DI/64, BN), 64>>>(A_log + (size_t)i*DI*DS,
                                             Dp + (size_t)i*DI);

        // out proj + residual (bf16 mma): h += y[TOK,512] @ ow[256,512]^T
        {
            dim3 grid(DM/GBN, TOK/GBM);
            mma_gemm_kernel<2><<<grid, 256, GEMM_SMEM>>>(
                p_y, DI, out_w + (size_t)i*DM*DI, p_h, DM, DI, DM);
        }
    }

    head_kernel<<<TOK/8, 256>>>(fn_g, fn_b, head_w, head_b, out);
    (void)in_sizes; (void)n_in; (void)out_size;
}

// round 6
// speedup vs baseline: 1.5554x; 1.5554x over previous
#include <cuda_runtime.h>
#include <math.h>
#include <cstdint>

#define BN 16
#define LL 1024
#define TOK (BN*LL)          // 16384 tokens
#define DM 256
#define DI 512
#define DS 16
#define DTR 16
#define NPROJ 48             // DTR + 2*DS

// ---------------- scratch (device globals; no allocation allowed) ------------
__device__ float g_h[TOK*DM];        // residual stream (b, l, m)
__device__ float g_xn[TOK*DM];       // layernormed
__device__ float g_xz[TOK*2*DI];     // in_proj output: [0:DI)=xin, [DI:2DI)=z
__device__ float g_u[TOK*DI];        // conv+silu output (u)
__device__ float g_proj[TOK*NPROJ];  // x_proj output: dt | B | C
__device__ float g_y[TOK*DI];        // scan output * silu(z)

// ---------------- helpers ----------------------------------------------------
__device__ __forceinline__ float sigmoidf_(float x) {
    return 1.f / (1.f + __expf(-x));
}
__device__ __forceinline__ float softplusf_(float x) {
    return (x > 20.f) ? x : log1pf(__expf(x));
}
__device__ __forceinline__ uint32_t smem_u32_(const void* p) {
    uint32_t a;
    asm("{ .reg .u64 t; cvta.to.shared.u64 t, %1; cvt.u32.u64 %0, t; }" : "=r"(a) : "l"(p));
    return a;
}
// pack two f32 -> bf16x2 (lo in lower half)
__device__ __forceinline__ uint32_t bf2_(float lo, float hi) {
    uint32_t r;
    asm("cvt.rn.bf16x2.f32 %0, %1, %2;" : "=r"(r) : "f"(hi), "f"(lo));
    return r;
}
#define LDSM4_(r0,r1,r2,r3,addr) \
    asm volatile("ldmatrix.sync.aligned.m8n8.x4.shared.b16 {%0,%1,%2,%3}, [%4];" \
        : "=r"(r0),"=r"(r1),"=r"(r2),"=r"(r3) : "r"(addr))
__device__ __forceinline__ void mma_bf16_(float* c, const uint32_t* a, const uint32_t* b) {
    asm volatile(
        "mma.sync.aligned.m16n8k16.row.col.f32.bf16.bf16.f32 "
        "{%0,%1,%2,%3}, {%4,%5,%6,%7}, {%8,%9}, {%0,%1,%2,%3};"
        : "+f"(c[0]), "+f"(c[1]), "+f"(c[2]), "+f"(c[3])
        : "r"(a[0]), "r"(a[1]), "r"(a[2]), "r"(a[3]), "r"(b[0]), "r"(b[1]));
}

// ---------------- bf16 tensor-core GEMM: C[M,N] = A[M,K] @ W[N,K]^T ----------
// CTA tile 128x128, BK=32, double-buffered SMEM, pitch-80B rows (LDSM
// conflict-free: 5 coprime 8). Warp tile 64x32. EPI 0: C=acc ; EPI 2: C+=acc.
#define GBM 128
#define GBN 128
#define GBK 32
#define PITCH 80u                        // bytes per 32-halves row
#define TILE_B (128u*PITCH)              // 10240 B
#define STAGE_B (2u*TILE_B)              // A + W
#define GEMM_SMEM (2u*STAGE_B)           // 40960 B

// load one 128x32 f32 sub-tile -> bf16 regs (4 rows x 4 cols per thread)
__device__ __forceinline__ void tile_ldg_bf_(const float* __restrict__ G, int ld,
                                             int row0, int rmax, int k0, int tid,
                                             uint2* r) {
    #pragma unroll
    for (int i = 0; i < 4; i++) {
        int row = row0 + i * 32 + (tid >> 3);
        if (row > rmax) row = rmax;
        int c4 = tid & 7;
        float4 v = *reinterpret_cast<const float4*>(G + (size_t)row * ld + k0 + c4 * 4);
        r[i].x = bf2_(v.x, v.y);
        r[i].y = bf2_(v.z, v.w);
    }
}
__device__ __forceinline__ void tile_sts_bf_(const uint2* r, char* S, int tid) {
    #pragma unroll
    for (int i = 0; i < 4; i++) {
        int row = i * 32 + (tid >> 3);
        int c4 = tid & 7;
        uint32_t off = (uint32_t)row * PITCH + (uint32_t)(c4 >> 1) * 16u + (uint32_t)(c4 & 1) * 8u;
        *reinterpret_cast<uint2*>(S + off) = r[i];
    }
}

template<int EPI>
__global__ __launch_bounds__(256) void mma_gemm_kernel(
        const float* __restrict__ A, int lda,
        const float* __restrict__ W,
        float* __restrict__ C, int ldc,
        int K, int NW) {
    extern __shared__ char smem[];
    uint32_t sbase = smem_u32_(smem);
    int tid = threadIdx.x;
    int wid = tid >> 5, lane = tid & 31;
    int g = lane >> 2, tg = lane & 3;
    int bm = blockIdx.y * GBM;
    int bn = blockIdx.x * GBN;
    int wm0 = (wid & 1) * 64;
    int wn0 = (wid >> 1) * 32;

    int rr = (lane & 7) + ((lane >> 3) & 1) * 8;   // row within 16
    int cc = (lane >> 4);                          // k-chunk select

    float acc[4][4][4];
    #pragma unroll
    for (int mf = 0; mf < 4; mf++)
        #pragma unroll
        for (int nf = 0; nf < 4; nf++)
            #pragma unroll
            for (int r = 0; r < 4; r++) acc[mf][nf][r] = 0.f;

    const int nst = K / GBK;

    {   // prologue: stage 0
        uint2 ra[4], rw[4];
        tile_ldg_bf_(A, lda, bm, TOK - 1, 0, tid, ra);
        tile_ldg_bf_(W, K,   bn, NW - 1,  0, tid, rw);
        tile_sts_bf_(ra, smem, tid);
        tile_sts_bf_(rw, smem + TILE_B, tid);
    }
    __syncthreads();

    for (int s = 0; s < nst; s++) {
        uint2 ra[4], rw[4];
        if (s + 1 < nst) {
            int k0 = (s + 1) * GBK;
            tile_ldg_bf_(A, lda, bm, TOK - 1, k0, tid, ra);
            tile_ldg_bf_(W, K,   bn, NW - 1,  k0, tid, rw);
        }
        uint32_t Sa = sbase + (uint32_t)(s & 1) * STAGE_B;
        uint32_t Sw = Sa + TILE_B;

        #pragma unroll
        for (int kk = 0; kk < 2; kk++) {
            uint32_t chunk_off = (uint32_t)(kk * 2 + cc) * 16u;
            uint32_t afr[4][4], bfr[4][2];
            #pragma unroll
            for (int mf = 0; mf < 4; mf++) {
                uint32_t ad = Sa + (uint32_t)(wm0 + mf * 16 + rr) * PITCH + chunk_off;
                LDSM4_(afr[mf][0], afr[mf][1], afr[mf][2], afr[mf][3], ad);
            }
            #pragma unroll
            for (int nh = 0; nh < 2; nh++) {
                uint32_t bd = Sw + (uint32_t)(wn0 + nh * 16 + rr) * PITCH + chunk_off;
                LDSM4_(bfr[2*nh][0], bfr[2*nh+1][0], bfr[2*nh][1], bfr[2*nh+1][1], bd);
            }
            #pragma unroll
            for (int mf = 0; mf < 4; mf++)
                #pragma unroll
                for (int nf = 0; nf < 4; nf++)
                    mma_bf16_(acc[mf][nf], afr[mf], bfr[nf]);
        }

        if (s + 1 < nst) {
            char* nb = smem + ((s + 1) & 1) * STAGE_B;
            tile_sts_bf_(ra, nb, tid);
            tile_sts_bf_(rw, nb + TILE_B, tid);
        }
        __syncthreads();
    }

    // epilogue: c0,c1 @(g, 2tg), c2,c3 @(g+8, 2tg)
    #pragma unroll
    for (int mf = 0; mf < 4; mf++) {
        int gr = bm + wm0 + mf * 16 + g;
        #pragma unroll
        for (int nf = 0; nf < 4; nf++) {
            int gc = bn + wn0 + nf * 8 + 2 * tg;
            if (gc >= NW) continue;
            float2 v01 = make_float2(acc[mf][nf][0], acc[mf][nf][1]);
            float2 v23 = make_float2(acc[mf][nf][2], acc[mf][nf][3]);
            float* p0 = C + (size_t)gr * ldc + gc;
            float* p1 = C + (size_t)(gr + 8) * ldc + gc;
            if (EPI == 2) {
                float2 o0 = *reinterpret_cast<float2*>(p0);
                float2 o1 = *reinterpret_cast<float2*>(p1);
                v01.x += o0.x; v01.y += o0.y;
                v23.x += o1.x; v23.y += o1.y;
            }
            *reinterpret_cast<float2*>(p0) = v01;
            *reinterpret_cast<float2*>(p1) = v23;
        }
    }
}

// ---------------- stem conv (k=3, pad=1) + relu ------------------------------
__global__ void stem_kernel(const float* __restrict__ x,
                            const float* __restrict__ sw,
                            const float* __restrict__ sb) {
    int t = blockIdx.x;
    int m = threadIdx.x;
    int b = t / LL, l = t % LL;
    __shared__ float xs[3][3];
    if (m < 9) {
        int c = m / 3, k = m % 3;
        int ll = l - 1 + k;
        xs[c][k] = (ll >= 0 && ll < LL) ? x[(b*3 + c)*LL + ll] : 0.f;
    }
    __syncthreads();
    float acc = sb[m];
    #pragma unroll
    for (int c = 0; c < 3; c++)
        #pragma unroll
        for (int k = 0; k < 3; k++)
            acc = fmaf(xs[c][k], sw[(m*3 + c)*3 + k], acc);
    g_h[t*DM + m] = fmaxf(acc, 0.f);
}

// ---------------- layernorm, warp-per-token (DM=256, 8 elems/lane) -----------
__device__ __forceinline__ float warp_sum_(float v) {
    #pragma unroll
    for (int o = 16; o; o >>= 1) v += __shfl_xor_sync(0xffffffffu, v, o);
    return v;
}
__global__ __launch_bounds__(256) void ln_kernel(const float* __restrict__ in,
                                                 const float* __restrict__ g,
                                                 const float* __restrict__ b,
                                                 float* __restrict__ out) {
    int wid = threadIdx.x >> 5, lane = threadIdx.x & 31;
    int t = blockIdx.x * 8 + wid;
    const float* row = in + (size_t)t * DM + lane * 8;
    float4 v0 = *reinterpret_cast<const float4*>(row);
    float4 v1 = *reinterpret_cast<const float4*>(row + 4);
    float s = v0.x+v0.y+v0.z+v0.w + v1.x+v1.y+v1.z+v1.w;
    float mean = warp_sum_(s) * (1.f / DM);
    float d0 = v0.x-mean, d1 = v0.y-mean, d2 = v0.z-mean, d3 = v0.w-mean;
    float d4 = v1.x-mean, d5 = v1.y-mean, d6 = v1.z-mean, d7 = v1.w-mean;
    float q = d0*d0+d1*d1+d2*d2+d3*d3+d4*d4+d5*d5+d6*d6+d7*d7;
    float rstd = rsqrtf(warp_sum_(q) * (1.f / DM) + 1e-5f);
    float4 g0 = *reinterpret_cast<const float4*>(g + lane * 8);
    float4 g1 = *reinterpret_cast<const float4*>(g + lane * 8 + 4);
    float4 b0 = *reinterpret_cast<const float4*>(b + lane * 8);
    float4 b1 = *reinterpret_cast<const float4*>(b + lane * 8 + 4);
    float* orow = out + (size_t)t * DM + lane * 8;
    float4 o0, o1;
    o0.x = d0*rstd*g0.x + b0.x; o0.y = d1*rstd*g0.y + b0.y;
    o0.z = d2*rstd*g0.z + b0.z; o0.w = d3*rstd*g0.w + b0.w;
    o1.x = d4*rstd*g1.x + b1.x; o1.y = d5*rstd*g1.y + b1.y;
    o1.z = d6*rstd*g1.z + b1.z; o1.w = d7*rstd*g1.w + b1.w;
    *reinterpret_cast<float4*>(orow) = o0;
    *reinterpret_cast<float4*>(orow + 4) = o1;
}

// ---------------- causal depthwise conv (k=4, left pad 3) + silu -------------
__global__ void conv_silu_kernel(const float* __restrict__ cw,
                                 const float* __restrict__ cb) {
    int idx = blockIdx.x * blockDim.x + threadIdx.x;
    if (idx >= TOK*DI) return;
    int d = idx % DI;
    int t = idx / DI;
    int l = t % LL;
    float acc = cb[d];
    #pragma unroll
    for (int k = 0; k < 4; k++) {
        int ls = l - 3 + k;
        if (ls >= 0)
            acc = fmaf(g_xz[(size_t)(t - 3 + k)*(2*DI) + d], cw[d*4 + k], acc);
    }
    g_u[idx] = acc * sigmoidf_(acc);
}

// ---------------- selective scan + fused delta-GEMM + gate -------------------
// grid (DI/128, BN), 128 threads. delta = softplus(dt[t,:]·dtw[d,:] + dtb[d])
// computed in-kernel (dt from smem broadcast, dtw row in regs).
// Fast path when A[s] == -(s+1): exp(dlt*A[s]) = q^(s+1), q = expf(-dlt).
#define SCH 8
__global__ __launch_bounds__(128) void scan_kernel(const float* __restrict__ Alog,
                                                   const float* __restrict__ Dp,
                                                   const float* __restrict__ dtw,
                                                   const float* __restrict__ dtb) {
    int b = blockIdx.y;
    int d = blockIdx.x * 128 + threadIdx.x;
    int tid = threadIdx.x;

    float A[DS], h[DS], wdt[DTR];
    bool fast = true;
    #pragma unroll
    for (int s = 0; s < DS; s++) {
        A[s] = -__expf(Alog[d*DS + s]);
        h[s] = 0.f;
        fast = fast && (fabsf(A[s] + (float)(s + 1)) < 1e-3f);
    }
    #pragma unroll
    for (int r = 0; r < DTR; r++) wdt[r] = dtw[d*DTR + r];
    float bdt = dtb[d];
    float Dd = Dp[d];

    __shared__ float sD[SCH][DTR];
    __shared__ float sB[SCH][DS];
    __shared__ float sC[SCH][DS];
    int t0 = b * LL;

    for (int l0 = 0; l0 < LL; l0 += SCH) {
        // cooperative load of proj rows: SCH * 48 = 384 floats, 128 thr * 3
        #pragma unroll
        for (int r = 0; r < 3; r++) {
            int i = tid + r*128;
            int step = i / NPROJ;
            int j = i - step * NPROJ;
            float val = g_proj[(size_t)(t0 + l0 + step)*NPROJ + j];
            if (j < DTR)         sD[step][j] = val;
            else if (j < DTR+DS) sB[step][j - DTR] = val;
            else                 sC[step][j - DTR - DS] = val;
        }
        __syncthreads();

        float uc[SCH], zc[SCH];
        #pragma unroll
        for (int i = 0; i < SCH; i++) {
            size_t t = (size_t)(t0 + l0 + i);
            uc[i] = g_u[t*DI + d];
            zc[i] = g_xz[t*2*DI + DI + d];
        }
        #pragma unroll
        for (int i = 0; i < SCH; i++) {
            float draw = bdt;
            #pragma unroll
            for (int r = 0; r < DTR; r++) draw = fmaf(sD[i][r], wdt[r], draw);
            float dlt = softplusf_(draw);
            float uu = uc[i];
            float du = dlt * uu;
            float y = 0.f;
            if (fast) {
                float q  = __expf(-dlt);
                float q2 = q*q, q4 = q2*q2, q8 = q4*q4;
                float ep[DS];
                ep[0]=q;        ep[1]=q2;       ep[2]=q2*q;     ep[3]=q4;
                ep[4]=q4*q;     ep[5]=q4*q2;    ep[6]=ep[5]*q;  ep[7]=q8;
                ep[8]=q8*q;     ep[9]=q8*q2;    ep[10]=ep[9]*q; ep[11]=q8*q4;
                ep[12]=ep[11]*q; ep[13]=ep[11]*q2; ep[14]=ep[13]*q; ep[15]=q8*q8;
                #pragma unroll
                for (int s = 0; s < DS; s++) {
                    h[s] = fmaf(h[s], ep[s], du * sB[i][s]);
                    y = fmaf(h[s], sC[i][s], y);
                }
            } else {
                #pragma unroll
                for (int s = 0; s < DS; s++) {
                    float ep = __expf(dlt * A[s]);
                    h[s] = fmaf(h[s], ep, du * sB[i][s]);
                    y = fmaf(h[s], sC[i][s], y);
                }
            }
            y = fmaf(uu, Dd, y);
            float zz = zc[i];
            y *= zz * sigmoidf_(zz);
            g_y[(size_t)(t0 + l0 + i)*DI + d] = y;
        }
        __syncthreads();
    }
}

// ---------------- final LN + head projection + sigmoid (warp/token) ----------
__global__ __launch_bounds__(256) void head_kernel(const float* __restrict__ g,
                                                   const float* __restrict__ b,
                                                   const float* __restrict__ hw,
                                                   const float* __restrict__ hb,
                                                   float* __restrict__ out) {
    int wid = threadIdx.x >> 5, lane = threadIdx.x & 31;
    int t = blockIdx.x * 8 + wid;
    const float* row = g_h + (size_t)t * DM + lane * 8;
    float4 v0 = *reinterpret_cast<const float4*>(row);
    float4 v1 = *reinterpret_cast<const float4*>(row + 4);
    float s = v0.x+v0.y+v0.z+v0.w + v1.x+v1.y+v1.z+v1.w;
    float mean = warp_sum_(s) * (1.f / DM);
    float d0 = v0.x-mean, d1 = v0.y-mean, d2 = v0.z-mean, d3 = v0.w-mean;
    float d4 = v1.x-mean, d5 = v1.y-mean, d6 = v1.z-mean, d7 = v1.w-mean;
    float q = d0*d0+d1*d1+d2*d2+d3*d3+d4*d4+d5*d5+d6*d6+d7*d7;
    float rstd = rsqrtf(warp_sum_(q) * (1.f / DM) + 1e-5f);
    float4 g0 = *reinterpret_cast<const float4*>(g + lane * 8);
    float4 g1 = *reinterpret_cast<const float4*>(g + lane * 8 + 4);
    float4 b0 = *reinterpret_cast<const float4*>(b + lane * 8);
    float4 b1 = *reinterpret_cast<const float4*>(b + lane * 8 + 4);
    float4 w0 = *reinterpret_cast<const float4*>(hw + lane * 8);
    float4 w1 = *reinterpret_cast<const float4*>(hw + lane * 8 + 4);
    float dot =
        (d0*rstd*g0.x + b0.x)*w0.x + (d1*rstd*g0.y + b0.y)*w0.y +
        (d2*rstd*g0.z + b0.z)*w0.z + (d3*rstd*g0.w + b0.w)*w0.w +
        (d4*rstd*g1.x + b1.x)*w1.x + (d5*rstd*g1.y + b1.y)*w1.y +
        (d6*rstd*g1.z + b1.z)*w1.z + (d7*rstd*g1.w + b1.w)*w1.w;
    float tot = warp_sum_(dot);
    if (lane == 0) out[t] = sigmoidf_(tot + hb[0]);
}

// ---------------- host launcher ----------------------------------------------
extern "C" void kernel_launch(void* const* d_in, const int* in_sizes, int n_in,
                              void* d_out, int out_size) {
    const float* x       = (const float*)d_in[0];
    const float* stem_w  = (const float*)d_in[1];
    const float* stem_b  = (const float*)d_in[2];
    const float* norm_g  = (const float*)d_in[3];
    const float* norm_b  = (const float*)d_in[4];
    const float* in_w    = (const float*)d_in[5];
    const float* conv_w  = (const float*)d_in[6];
    const float* conv_b  = (const float*)d_in[7];
    const float* xpw     = (const float*)d_in[8];
    const float* dtw     = (const float*)d_in[9];
    const float* dtb     = (const float*)d_in[10];
    const float* A_log   = (const float*)d_in[11];
    const float* Dp      = (const float*)d_in[12];
    const float* out_w   = (const float*)d_in[13];
    const float* fn_g    = (const float*)d_in[14];
    const float* fn_b    = (const float*)d_in[15];
    const float* head_w  = (const float*)d_in[16];
    const float* head_b  = (const float*)d_in[17];
    float* out = (float*)d_out;

    float *p_h, *p_xn, *p_xz, *p_u, *p_proj, *p_y;
    cudaGetSymbolAddress((void**)&p_h,     g_h);
    cudaGetSymbolAddress((void**)&p_xn,    g_xn);
    cudaGetSymbolAddress((void**)&p_xz,    g_xz);
    cudaGetSymbolAddress((void**)&p_u,     g_u);
    cudaGetSymbolAddress((void**)&p_proj,  g_proj);
    cudaGetSymbolAddress((void**)&p_y,     g_y);

    cudaFuncSetAttribute(mma_gemm_kernel<0>,
                         cudaFuncAttributeMaxDynamicSharedMemorySize, GEMM_SMEM);
    cudaFuncSetAttribute(mma_gemm_kernel<2>,
                         cudaFuncAttributeMaxDynamicSharedMemorySize, GEMM_SMEM);

    stem_kernel<<<TOK, 256>>>(x, stem_w, stem_b);

    for (int i = 0; i < 4; i++) {
        ln_kernel<<<TOK/8, 256>>>(p_h, norm_g + i*DM, norm_b + i*DM, p_xn);

        // in_proj (bf16 mma): [TOK,1024] = xn[TOK,256] @ W[1024,256]^T
        {
            dim3 grid((2*DI)/GBN, TOK/GBM);
            mma_gemm_kernel<0><<<grid, 256, GEMM_SMEM>>>(
                p_xn, DM, in_w + (size_t)i*2*DI*DM, p_xz, 2*DI, DM, 2*DI);
        }

        conv_silu_kernel<<<(TOK*DI + 255)/256, 256>>>(conv_w + (size_t)i*DI*4,
                                                      conv_b + (size_t)i*DI);

        // x_proj (bf16 mma, N=48 padded to tile): [TOK,48] = u @ xw^T
        {
            dim3 grid(1, TOK/GBM);
            mma_gemm_kernel<0><<<grid, 256, GEMM_SMEM>>>(
                p_u, DI, xpw + (size_t)i*NPROJ*DI, p_proj, NPROJ, DI, NPROJ);
        }

        // scan + fused delta + gate
        {
            dim3 grid(DI/128, BN);
            scan_kernel<<<grid, 128>>>(A_log + (size_t)i*DI*DS, Dp + (size_t)i*DI,
                                       dtw + (size_t)i*DI*DTR, dtb + (size_t)i*DI);
        }

        // out proj + residual (bf16 mma): h += y[TOK,512] @ ow[256,512]^T
        {
            dim3 grid(DM/GBN, TOK/GBM);
            mma_gemm_kernel<2><<<grid, 256, GEMM_SMEM>>>(
                p_y, DI, out_w + (size_t)i*DM*DI, p_h, DM, DI, DM);
        }
    }

    head_kernel<<<TOK/8, 256>>>(fn_g, fn_b, head_w, head_b, out);
    (void)in_sizes; (void)n_in; (void)out_size;
}

// round 7
// speedup vs baseline: 1.6175x; 1.0399x over previous
#include <cuda_runtime.h>
#include <cuda_bf16.h>
#include <math.h>
#include <cstdint>

#define BN 16
#define LL 1024
#define TOK (BN*LL)          // 16384 tokens
#define DM 256
#define DI 512
#define DS 16
#define DTR 16
#define NPROJ 48             // DTR + 2*DS

// ---------------- scratch (device globals; no allocation allowed) ------------
__device__ float g_h[TOK*DM];        // residual stream (b, l, m)
__device__ float g_xz[TOK*2*DI];     // in_proj output: [0:DI)=xin, [DI:2DI)=z
__device__ float g_u[TOK*DI];        // conv+silu output (f32, for scan)
__device__ float g_proj[TOK*NPROJ];  // x_proj output: dt | B | C

__device__ __align__(256) __nv_bfloat16 g_xn_bf[TOK*DM];   // LN output (GEMM A)
__device__ __align__(256) __nv_bfloat16 g_u_bf[TOK*DI];    // conv output (GEMM A)
__device__ __align__(256) __nv_bfloat16 g_y_bf[TOK*DI];    // scan output (GEMM A)
__device__ __align__(256) __nv_bfloat16 g_inw_bf[4*1024*256];
__device__ __align__(256) __nv_bfloat16 g_xpw_bf[4*128*512];  // padded 48->128
__device__ __align__(256) __nv_bfloat16 g_outw_bf[4*256*512];

// ---------------- helpers ----------------------------------------------------
__device__ __forceinline__ float sigmoidf_(float x) {
    return 1.f / (1.f + __expf(-x));
}
__device__ __forceinline__ float softplusf_(float x) {
    return (x > 20.f) ? x : log1pf(__expf(x));
}
__device__ __forceinline__ uint32_t smem_u32_(const void* p) {
    uint32_t a;
    asm("{ .reg .u64 t; cvta.to.shared.u64 t, %1; cvt.u32.u64 %0, t; }" : "=r"(a) : "l"(p));
    return a;
}
// pack two f32 -> bf16x2 (lo in lower half)
__device__ __forceinline__ uint32_t bf2_(float lo, float hi) {
    uint32_t r;
    asm("cvt.rn.bf16x2.f32 %0, %1, %2;" : "=r"(r) : "f"(hi), "f"(lo));
    return r;
}
#define LDSM4_(r0,r1,r2,r3,addr) \
    asm volatile("ldmatrix.sync.aligned.m8n8.x4.shared.b16 {%0,%1,%2,%3}, [%4];" \
        : "=r"(r0),"=r"(r1),"=r"(r2),"=r"(r3) : "r"(addr))
__device__ __forceinline__ void mma_bf16_(float* c, const uint32_t* a, const uint32_t* b) {
    asm volatile(
        "mma.sync.aligned.m16n8k16.row.col.f32.bf16.bf16.f32 "
        "{%0,%1,%2,%3}, {%4,%5,%6,%7}, {%8,%9}, {%0,%1,%2,%3};"
        : "+f"(c[0]), "+f"(c[1]), "+f"(c[2]), "+f"(c[3])
        : "r"(a[0]), "r"(a[1]), "r"(a[2]), "r"(a[3]), "r"(b[0]), "r"(b[1]));
}

// ---------------- bf16 GEMM w/ cp.async: C[M,N] = A[M,K] @ W[N,K]^T ----------
// CTA 128x128, BK=32, 3-stage cp.async ring, pitch-80 SMEM rows (conflict-free
// LDSM). Warp tile 64x32. EPI 0: C=acc ; EPI 2: C+=acc. W rows padded to 128.
#define GBM 128
#define GBN 128
#define GBK 32
#define PITCH 80u                        // bytes per 32-bf16 row
#define TILE_B (128u*PITCH)              // 10240 B
#define STAGE_B (2u*TILE_B)              // A + W
#define NSTAGE 3
#define GEMM_SMEM (NSTAGE*STAGE_B)       // 61440 B

// issue async copy of one 128x32 bf16 tile (512 16B chunks / 256 threads)
__device__ __forceinline__ void cp_tile_(const __nv_bfloat16* __restrict__ G, int ld,
                                         int row0, int k0, uint32_t sb, int tid) {
    #pragma unroll
    for (int i = 0; i < 2; i++) {
        int cid = tid + i * 256;         // 0..511
        int row = cid >> 2;
        int c = cid & 3;
        uint32_t dst = sb + (uint32_t)row * PITCH + (uint32_t)c * 16u;
        const void* src = G + (size_t)(row0 + row) * ld + k0 + c * 8;
        asm volatile("cp.async.ca.shared.global [%0], [%1], 16;" :: "r"(dst), "l"(src));
    }
}

template<int EPI>
__global__ __launch_bounds__(256, 2) void mma_gemm_kernel(
        const __nv_bfloat16* __restrict__ A, int lda,
        const __nv_bfloat16* __restrict__ W,
        float* __restrict__ C, int ldc,
        int K, int NW) {
    extern __shared__ char smem[];
    uint32_t sbase = smem_u32_(smem);
    int tid = threadIdx.x;
    int wid = tid >> 5, lane = tid & 31;
    int g = lane >> 2, tg = lane & 3;
    int bm = blockIdx.y * GBM;
    int bn = blockIdx.x * GBN;
    int wm0 = (wid & 1) * 64;
    int wn0 = (wid >> 1) * 32;

    int rr = (lane & 7) + ((lane >> 3) & 1) * 8;   // ldmatrix row within 16
    int cc = (lane >> 4);                          // ldmatrix k-chunk select

    float acc[4][4][4];
    #pragma unroll
    for (int mf = 0; mf < 4; mf++)
        #pragma unroll
        for (int nf = 0; nf < 4; nf++)
            #pragma unroll
            for (int r = 0; r < 4; r++) acc[mf][nf][r] = 0.f;

    const int nst = K / GBK;

    // prologue: stages 0,1
    #pragma unroll
    for (int p = 0; p < NSTAGE - 1; p++) {
        uint32_t sb = sbase + (uint32_t)p * STAGE_B;
        cp_tile_(A, lda, bm, p * GBK, sb, tid);
        cp_tile_(W, K,   bn, p * GBK, sb + TILE_B, tid);
        asm volatile("cp.async.commit_group;" ::: "memory");
    }

    for (int s = 0; s < nst; s++) {
        asm volatile("cp.async.wait_group 1;" ::: "memory");
        __syncthreads();
        uint32_t Sa = sbase + (uint32_t)(s % NSTAGE) * STAGE_B;
        uint32_t Sw = Sa + TILE_B;

        #pragma unroll
        for (int kk = 0; kk < 2; kk++) {
            uint32_t chunk_off = (uint32_t)(kk * 2 + cc) * 16u;
            uint32_t afr[4][4], bfr[4][2];
            #pragma unroll
            for (int mf = 0; mf < 4; mf++) {
                uint32_t ad = Sa + (uint32_t)(wm0 + mf * 16 + rr) * PITCH + chunk_off;
                LDSM4_(afr[mf][0], afr[mf][1], afr[mf][2], afr[mf][3], ad);
            }
            #pragma unroll
            for (int nh = 0; nh < 2; nh++) {
                uint32_t bd = Sw + (uint32_t)(wn0 + nh * 16 + rr) * PITCH + chunk_off;
                LDSM4_(bfr[2*nh][0], bfr[2*nh+1][0], bfr[2*nh][1], bfr[2*nh+1][1], bd);
            }
            #pragma unroll
            for (int mf = 0; mf < 4; mf++)
                #pragma unroll
                for (int nf = 0; nf < 4; nf++)
                    mma_bf16_(acc[mf][nf], afr[mf], bfr[nf]);
        }

        if (s + 2 < nst) {
            uint32_t nb = sbase + (uint32_t)((s + 2) % NSTAGE) * STAGE_B;
            cp_tile_(A, lda, bm, (s + 2) * GBK, nb, tid);
            cp_tile_(W, K,   bn, (s + 2) * GBK, nb + TILE_B, tid);
        }
        asm volatile("cp.async.commit_group;" ::: "memory");
    }

    // epilogue: c0,c1 @(g, 2tg), c2,c3 @(g+8, 2tg)
    #pragma unroll
    for (int mf = 0; mf < 4; mf++) {
        int gr = bm + wm0 + mf * 16 + g;
        #pragma unroll
        for (int nf = 0; nf < 4; nf++) {
            int gc = bn + wn0 + nf * 8 + 2 * tg;
            if (gc >= NW) continue;
            float2 v01 = make_float2(acc[mf][nf][0], acc[mf][nf][1]);
            float2 v23 = make_float2(acc[mf][nf][2], acc[mf][nf][3]);
            float* p0 = C + (size_t)gr * ldc + gc;
            float* p1 = C + (size_t)(gr + 8) * ldc + gc;
            if (EPI == 2) {
                float2 o0 = *reinterpret_cast<float2*>(p0);
                float2 o1 = *reinterpret_cast<float2*>(p1);
                v01.x += o0.x; v01.y += o0.y;
                v23.x += o1.x; v23.y += o1.y;
            }
            *reinterpret_cast<float2*>(p0) = v01;
            *reinterpret_cast<float2*>(p1) = v23;
        }
    }
}

// ---------------- weight conversion (all layers, once per launch) ------------
#define INW_E  (4*1024*256)
#define XPW_E  (4*128*512)
#define OUTW_E (4*256*512)
__global__ void wconv_kernel(const float* __restrict__ in_w,
                             const float* __restrict__ xpw,
                             const float* __restrict__ out_w) {
    int i = blockIdx.x * 256 + threadIdx.x;
    if (i < INW_E) {
        g_inw_bf[i] = __float2bfloat16(in_w[i]);
        return;
    }
    int j = i - INW_E;
    if (j < XPW_E) {
        int layer = j >> 16;            // 128*512
        int r = (j >> 9) & 127;
        int c = j & 511;
        float v = (r < NPROJ) ? xpw[((size_t)layer * NPROJ + r) * 512 + c] : 0.f;
        g_xpw_bf[j] = __float2bfloat16(v);
        return;
    }
    int k = j - XPW_E;
    if (k < OUTW_E) g_outw_bf[k] = __float2bfloat16(out_w[k]);
}

// ---------------- stem conv (k=3, pad=1) + relu ------------------------------
__global__ void stem_kernel(const float* __restrict__ x,
                            const float* __restrict__ sw,
                            const float* __restrict__ sb) {
    int t = blockIdx.x;
    int m = threadIdx.x;
    int b = t / LL, l = t % LL;
    __shared__ float xs[3][3];
    if (m < 9) {
        int c = m / 3, k = m % 3;
        int ll = l - 1 + k;
        xs[c][k] = (ll >= 0 && ll < LL) ? x[(b*3 + c)*LL + ll] : 0.f;
    }
    __syncthreads();
    float acc = sb[m];
    #pragma unroll
    for (int c = 0; c < 3; c++)
        #pragma unroll
        for (int k = 0; k < 3; k++)
            acc = fmaf(xs[c][k], sw[(m*3 + c)*3 + k], acc);
    g_h[t*DM + m] = fmaxf(acc, 0.f);
}

// ---------------- layernorm -> bf16, warp-per-token --------------------------
__device__ __forceinline__ float warp_sum_(float v) {
    #pragma unroll
    for (int o = 16; o; o >>= 1) v += __shfl_xor_sync(0xffffffffu, v, o);
    return v;
}
__global__ __launch_bounds__(256) void ln_kernel(const float* __restrict__ in,
                                                 const float* __restrict__ g,
                                                 const float* __restrict__ b) {
    int wid = threadIdx.x >> 5, lane = threadIdx.x & 31;
    int t = blockIdx.x * 8 + wid;
    const float* row = in + (size_t)t * DM + lane * 8;
    float4 v0 = *reinterpret_cast<const float4*>(row);
    float4 v1 = *reinterpret_cast<const float4*>(row + 4);
    float s = v0.x+v0.y+v0.z+v0.w + v1.x+v1.y+v1.z+v1.w;
    float mean = warp_sum_(s) * (1.f / DM);
    float d0 = v0.x-mean, d1 = v0.y-mean, d2 = v0.z-mean, d3 = v0.w-mean;
    float d4 = v1.x-mean, d5 = v1.y-mean, d6 = v1.z-mean, d7 = v1.w-mean;
    float q = d0*d0+d1*d1+d2*d2+d3*d3+d4*d4+d5*d5+d6*d6+d7*d7;
    float rstd = rsqrtf(warp_sum_(q) * (1.f / DM) + 1e-5f);
    float4 g0 = *reinterpret_cast<const float4*>(g + lane * 8);
    float4 g1 = *reinterpret_cast<const float4*>(g + lane * 8 + 4);
    float4 b0 = *reinterpret_cast<const float4*>(b + lane * 8);
    float4 b1 = *reinterpret_cast<const float4*>(b + lane * 8 + 4);
    uint4 o;
    o.x = bf2_(d0*rstd*g0.x + b0.x, d1*rstd*g0.y + b0.y);
    o.y = bf2_(d2*rstd*g0.z + b0.z, d3*rstd*g0.w + b0.w);
    o.z = bf2_(d4*rstd*g1.x + b1.x, d5*rstd*g1.y + b1.y);
    o.w = bf2_(d6*rstd*g1.z + b1.z, d7*rstd*g1.w + b1.w);
    *reinterpret_cast<uint4*>(g_xn_bf + (size_t)t * DM + lane * 8) = o;
}

// ---------------- causal depthwise conv (k=4, left pad 3) + silu -------------
__global__ void conv_silu_kernel(const float* __restrict__ cw,
                                 const float* __restrict__ cb) {
    int idx = blockIdx.x * blockDim.x + threadIdx.x;
    if (idx >= TOK*DI) return;
    int d = idx % DI;
    int t = idx / DI;
    int l = t % LL;
    float acc = cb[d];
    #pragma unroll
    for (int k = 0; k < 4; k++) {
        int ls = l - 3 + k;
        if (ls >= 0)
            acc = fmaf(g_xz[(size_t)(t - 3 + k)*(2*DI) + d], cw[d*4 + k], acc);
    }
    float r = acc * sigmoidf_(acc);
    g_u[idx] = r;
    g_u_bf[idx] = __float2bfloat16(r);
}

// ---------------- selective scan + fused delta-GEMM + gate -------------------
// grid (DI/128, BN), 128 threads. delta = softplus(dt[t,:]·dtw[d,:] + dtb[d]).
// Fast path when A[s] == -(s+1): exp(dlt*A[s]) = q^(s+1), q = expf(-dlt).
#define SCH 8
__global__ __launch_bounds__(128) void scan_kernel(const float* __restrict__ Alog,
                                                   const float* __restrict__ Dp,
                                                   const float* __restrict__ dtw,
                                                   const float* __restrict__ dtb) {
    int b = blockIdx.y;
    int d = blockIdx.x * 128 + threadIdx.x;
    int tid = threadIdx.x;

    float A[DS], h[DS], wdt[DTR];
    bool fast = true;
    #pragma unroll
    for (int s = 0; s < DS; s++) {
        A[s] = -__expf(Alog[d*DS + s]);
        h[s] = 0.f;
        fast = fast && (fabsf(A[s] + (float)(s + 1)) < 1e-3f);
    }
    #pragma unroll
    for (int r = 0; r < DTR; r++) wdt[r] = dtw[d*DTR + r];
    float bdt = dtb[d];
    float Dd = Dp[d];

    __shared__ float sD[SCH][DTR];
    __shared__ float sB[SCH][DS];
    __shared__ float sC[SCH][DS];
    int t0 = b * LL;

    for (int l0 = 0; l0 < LL; l0 += SCH) {
        #pragma unroll
        for (int r = 0; r < 3; r++) {
            int i = tid + r*128;
            int step = i / NPROJ;
            int j = i - step * NPROJ;
            float val = g_proj[(size_t)(t0 + l0 + step)*NPROJ + j];
            if (j < DTR)         sD[step][j] = val;
            else if (j < DTR+DS) sB[step][j - DTR] = val;
            else                 sC[step][j - DTR - DS] = val;
        }
        __syncthreads();

        float uc[SCH], zc[SCH];
        #pragma unroll
        for (int i = 0; i < SCH; i++) {
            size_t t = (size_t)(t0 + l0 + i);
            uc[i] = g_u[t*DI + d];
            zc[i] = g_xz[t*2*DI + DI + d];
        }
        #pragma unroll
        for (int i = 0; i < SCH; i++) {
            float draw = bdt;
            #pragma unroll
            for (int r = 0; r < DTR; r++) draw = fmaf(sD[i][r], wdt[r], draw);
            float dlt = softplusf_(draw);
            float uu = uc[i];
            float du = dlt * uu;
            float y = 0.f;
            if (fast) {
                float q  = __expf(-dlt);
                float q2 = q*q, q4 = q2*q2, q8 = q4*q4;
                float ep[DS];
                ep[0]=q;        ep[1]=q2;       ep[2]=q2*q;     ep[3]=q4;
                ep[4]=q4*q;     ep[5]=q4*q2;    ep[6]=ep[5]*q;  ep[7]=q8;
                ep[8]=q8*q;     ep[9]=q8*q2;    ep[10]=ep[9]*q; ep[11]=q8*q4;
                ep[12]=ep[11]*q; ep[13]=ep[11]*q2; ep[14]=ep[13]*q; ep[15]=q8*q8;
                #pragma unroll
                for (int s = 0; s < DS; s++) {
                    h[s] = fmaf(h[s], ep[s], du * sB[i][s]);
                    y = fmaf(h[s], sC[i][s], y);
                }
            } else {
                #pragma unroll
                for (int s = 0; s < DS; s++) {
                    float ep = __expf(dlt * A[s]);
                    h[s] = fmaf(h[s], ep, du * sB[i][s]);
                    y = fmaf(h[s], sC[i][s], y);
                }
            }
            y = fmaf(uu, Dd, y);
            float zz = zc[i];
            y *= zz * sigmoidf_(zz);
            g_y_bf[(size_t)(t0 + l0 + i)*DI + d] = __float2bfloat16(y);
        }
        __syncthreads();
    }
}

// ---------------- final LN + head projection + sigmoid (warp/token) ----------
__global__ __launch_bounds__(256) void head_kernel(const float* __restrict__ g,
                                                   const float* __restrict__ b,
                                                   const float* __restrict__ hw,
                                                   const float* __restrict__ hb,
                                                   float* __restrict__ out) {
    int wid = threadIdx.x >> 5, lane = threadIdx.x & 31;
    int t = blockIdx.x * 8 + wid;
    const float* row = g_h + (size_t)t * DM + lane * 8;
    float4 v0 = *reinterpret_cast<const float4*>(row);
    float4 v1 = *reinterpret_cast<const float4*>(row + 4);
    float s = v0.x+v0.y+v0.z+v0.w + v1.x+v1.y+v1.z+v1.w;
    float mean = warp_sum_(s) * (1.f / DM);
    float d0 = v0.x-mean, d1 = v0.y-mean, d2 = v0.z-mean, d3 = v0.w-mean;
    float d4 = v1.x-mean, d5 = v1.y-mean, d6 = v1.z-mean, d7 = v1.w-mean;
    float q = d0*d0+d1*d1+d2*d2+d3*d3+d4*d4+d5*d5+d6*d6+d7*d7;
    float rstd = rsqrtf(warp_sum_(q) * (1.f / DM) + 1e-5f);
    float4 g0 = *reinterpret_cast<const float4*>(g + lane * 8);
    float4 g1 = *reinterpret_cast<const float4*>(g + lane * 8 + 4);
    float4 b0 = *reinterpret_cast<const float4*>(b + lane * 8);
    float4 b1 = *reinterpret_cast<const float4*>(b + lane * 8 + 4);
    float4 w0 = *reinterpret_cast<const float4*>(hw + lane * 8);
    float4 w1 = *reinterpret_cast<const float4*>(hw + lane * 8 + 4);
    float dot =
        (d0*rstd*g0.x + b0.x)*w0.x + (d1*rstd*g0.y + b0.y)*w0.y +
        (d2*rstd*g0.z + b0.z)*w0.z + (d3*rstd*g0.w + b0.w)*w0.w +
        (d4*rstd*g1.x + b1.x)*w1.x + (d5*rstd*g1.y + b1.y)*w1.y +
        (d6*rstd*g1.z + b1.z)*w1.z + (d7*rstd*g1.w + b1.w)*w1.w;
    float tot = warp_sum_(dot);
    if (lane == 0) out[t] = sigmoidf_(tot + hb[0]);
}

// ---------------- host launcher ----------------------------------------------
extern "C" void kernel_launch(void* const* d_in, const int* in_sizes, int n_in,
                              void* d_out, int out_size) {
    const float* x       = (const float*)d_in[0];
    const float* stem_w  = (const float*)d_in[1];
    const float* stem_b  = (const float*)d_in[2];
    const float* norm_g  = (const float*)d_in[3];
    const float* norm_b  = (const float*)d_in[4];
    const float* in_w    = (const float*)d_in[5];
    const float* conv_w  = (const float*)d_in[6];
    const float* conv_b  = (const float*)d_in[7];
    const float* xpw     = (const float*)d_in[8];
    const float* dtw     = (const float*)d_in[9];
    const float* dtb     = (const float*)d_in[10];
    const float* A_log   = (const float*)d_in[11];
    const float* Dp      = (const float*)d_in[12];
    const float* out_w   = (const float*)d_in[13];
    const float* fn_g    = (const float*)d_in[14];
    const float* fn_b    = (const float*)d_in[15];
    const float* head_w  = (const float*)d_in[16];
    const float* head_b  = (const float*)d_in[17];
    float* out = (float*)d_out;

    float *p_h, *p_xz, *p_u, *p_proj;
    __nv_bfloat16 *p_xn_bf, *p_u_bf, *p_y_bf, *p_inw, *p_xpw, *p_outw;
    cudaGetSymbolAddress((void**)&p_h,     g_h);
    cudaGetSymbolAddress((void**)&p_xz,    g_xz);
    cudaGetSymbolAddress((void**)&p_u,     g_u);
    cudaGetSymbolAddress((void**)&p_proj,  g_proj);
    cudaGetSymbolAddress((void**)&p_xn_bf, g_xn_bf);
    cudaGetSymbolAddress((void**)&p_u_bf,  g_u_bf);
    cudaGetSymbolAddress((void**)&p_y_bf,  g_y_bf);
    cudaGetSymbolAddress((void**)&p_inw,   g_inw_bf);
    cudaGetSymbolAddress((void**)&p_xpw,   g_xpw_bf);
    cudaGetSymbolAddress((void**)&p_outw,  g_outw_bf);

    cudaFuncSetAttribute(mma_gemm_kernel<0>,
                         cudaFuncAttributeMaxDynamicSharedMemorySize, GEMM_SMEM);
    cudaFuncSetAttribute(mma_gemm_kernel<2>,
                         cudaFuncAttributeMaxDynamicSharedMemorySize, GEMM_SMEM);

    wconv_kernel<<<(INW_E + XPW_E + OUTW_E)/256, 256>>>(in_w, xpw, out_w);
    stem_kernel<<<TOK, 256>>>(x, stem_w, stem_b);

    for (int i = 0; i < 4; i++) {
        ln_kernel<<<TOK/8, 256>>>(p_h, norm_g + i*DM, norm_b + i*DM);

        // in_proj (bf16 mma + cp.async): [TOK,1024] = xn @ W^T
        {
            dim3 grid((2*DI)/GBN, TOK/GBM);
            mma_gemm_kernel<0><<<grid, 256, GEMM_SMEM>>>(
                p_xn_bf, DM, p_inw + (size_t)i*1024*256, p_xz, 2*DI, DM, 2*DI);
        }

        conv_silu_kernel<<<(TOK*DI + 255)/256, 256>>>(conv_w + (size_t)i*DI*4,
                                                      conv_b + (size_t)i*DI);

        // x_proj: [TOK,48] = u @ xw^T (W padded to 128 rows)
        {
            dim3 grid(1, TOK/GBM);
            mma_gemm_kernel<0><<<grid, 256, GEMM_SMEM>>>(
                p_u_bf, DI, p_xpw + (size_t)i*128*512, p_proj, NPROJ, DI, NPROJ);
        }

        // scan + fused delta + gate
        {
            dim3 grid(DI/128, BN);
            scan_kernel<<<grid, 128>>>(A_log + (size_t)i*DI*DS, Dp + (size_t)i*DI,
                                       dtw + (size_t)i*DI*DTR, dtb + (size_t)i*DI);
        }

        // out proj + residual: h += y @ ow^T
        {
            dim3 grid(DM/GBN, TOK/GBM);
            mma_gemm_kernel<2><<<grid, 256, GEMM_SMEM>>>(
                p_y_bf, DI, p_outw + (size_t)i*256*512, p_h, DM, DI, DM);
        }
    }

    head_kernel<<<TOK/8, 256>>>(fn_g, fn_b, head_w, head_b, out);
    (void)in_sizes; (void)n_in; (void)out_size;
}

// round 9
// speedup vs baseline: 1.6797x; 1.0384x over previous
#include <cuda_runtime.h>
#include <cuda_bf16.h>
#include <math.h>
#include <cstdint>

#define BN 16
#define LL 1024
#define TOK (BN*LL)          // 16384 tokens
#define DM 256
#define DI 512
#define DS 16
#define DTR 16
#define NPROJ 48             // DTR + 2*DS

// ---------------- scratch (device globals; no allocation allowed) ------------
__device__ float g_h[TOK*DM];        // residual stream (b, l, m)
__device__ float g_xz[TOK*2*DI];     // in_proj output: [0:DI)=xin, [DI:2DI)=z
__device__ float g_u[TOK*DI];        // conv+silu output (f32, for scan)
__device__ float g_proj[TOK*NPROJ];  // x_proj output: dt | B | C

__device__ __align__(256) __nv_bfloat16 g_xn_bf[TOK*DM];   // LN output (GEMM A)
__device__ __align__(256) __nv_bfloat16 g_u_bf[TOK*DI];    // conv output (GEMM A)
__device__ __align__(256) __nv_bfloat16 g_y_bf[TOK*DI];    // scan output (GEMM A)
__device__ __align__(256) __nv_bfloat16 g_inw_bf[4*1024*256];
__device__ __align__(256) __nv_bfloat16 g_xpw_bf[4*128*512];  // padded 48->128
__device__ __align__(256) __nv_bfloat16 g_outw_bf[4*256*512];

// ---------------- helpers ----------------------------------------------------
__device__ __forceinline__ float sigmoidf_(float x) {
    return 1.f / (1.f + __expf(-x));
}
__device__ __forceinline__ float softplusf_(float x) {
    return (x > 20.f) ? x : log1pf(__expf(x));
}
__device__ __forceinline__ uint32_t smem_u32_(const void* p) {
    uint32_t a;
    asm("{ .reg .u64 t; cvta.to.shared.u64 t, %1; cvt.u32.u64 %0, t; }" : "=r"(a) : "l"(p));
    return a;
}
// pack two f32 -> bf16x2 (lo in lower half)
__device__ __forceinline__ uint32_t bf2_(float lo, float hi) {
    uint32_t r;
    asm("cvt.rn.bf16x2.f32 %0, %1, %2;" : "=r"(r) : "f"(hi), "f"(lo));
    return r;
}
#define LDSM4_(r0,r1,r2,r3,addr) \
    asm volatile("ldmatrix.sync.aligned.m8n8.x4.shared.b16 {%0,%1,%2,%3}, [%4];" \
        : "=r"(r0),"=r"(r1),"=r"(r2),"=r"(r3) : "r"(addr))
__device__ __forceinline__ void mma_bf16_(float* c, const uint32_t* a, const uint32_t* b) {
    asm volatile(
        "mma.sync.aligned.m16n8k16.row.col.f32.bf16.bf16.f32 "
        "{%0,%1,%2,%3}, {%4,%5,%6,%7}, {%8,%9}, {%0,%1,%2,%3};"
        : "+f"(c[0]), "+f"(c[1]), "+f"(c[2]), "+f"(c[3])
        : "r"(a[0]), "r"(a[1]), "r"(a[2]), "r"(a[3]), "r"(b[0]), "r"(b[1]));
}

// ---------------- bf16 GEMM w/ cp.async: C[M,N] = A[M,K] @ W[N,K]^T ----------
// CTA 128x128, BK=32, 3-stage cp.async ring, pitch-80 SMEM rows (conflict-free
// LDSM). Warp tile 64x32. EPI 0: C=acc ; EPI 2: C+=acc. W rows padded to 128.
#define GBM 128
#define GBN 128
#define GBK 32
#define PITCH 80u                        // bytes per 32-bf16 row
#define TILE_B (128u*PITCH)              // 10240 B
#define STAGE_B (2u*TILE_B)              // A + W
#define NSTAGE 3
#define GEMM_SMEM (NSTAGE*STAGE_B)       // 61440 B

// issue async copy of one 128x32 bf16 tile (512 16B chunks / 256 threads)
__device__ __forceinline__ void cp_tile_(const __nv_bfloat16* __restrict__ G, int ld,
                                         int row0, int k0, uint32_t sb, int tid) {
    #pragma unroll
    for (int i = 0; i < 2; i++) {
        int cid = tid + i * 256;         // 0..511
        int row = cid >> 2;
        int c = cid & 3;
        uint32_t dst = sb + (uint32_t)row * PITCH + (uint32_t)c * 16u;
        const void* src = G + (size_t)(row0 + row) * ld + k0 + c * 8;
        asm volatile("cp.async.ca.shared.global [%0], [%1], 16;" :: "r"(dst), "l"(src));
    }
}

template<int EPI>
__global__ __launch_bounds__(256, 2) void mma_gemm_kernel(
        const __nv_bfloat16* __restrict__ A, int lda,
        const __nv_bfloat16* __restrict__ W,
        float* __restrict__ C, int ldc,
        int K, int NW) {
    extern __shared__ char smem[];
    uint32_t sbase = smem_u32_(smem);
    int tid = threadIdx.x;
    int wid = tid >> 5, lane = tid & 31;
    int g = lane >> 2, tg = lane & 3;
    int bm = blockIdx.y * GBM;
    int bn = blockIdx.x * GBN;
    int wm0 = (wid & 1) * 64;
    int wn0 = (wid >> 1) * 32;

    int rr = (lane & 7) + ((lane >> 3) & 1) * 8;   // ldmatrix row within 16
    int cc = (lane >> 4);                          // ldmatrix k-chunk select

    float acc[4][4][4];
    #pragma unroll
    for (int mf = 0; mf < 4; mf++)
        #pragma unroll
        for (int nf = 0; nf < 4; nf++)
            #pragma unroll
            for (int r = 0; r < 4; r++) acc[mf][nf][r] = 0.f;

    const int nst = K / GBK;

    // prologue: stages 0,1
    #pragma unroll
    for (int p = 0; p < NSTAGE - 1; p++) {
        uint32_t sb = sbase + (uint32_t)p * STAGE_B;
        cp_tile_(A, lda, bm, p * GBK, sb, tid);
        cp_tile_(W, K,   bn, p * GBK, sb + TILE_B, tid);
        asm volatile("cp.async.commit_group;" ::: "memory");
    }

    for (int s = 0; s < nst; s++) {
        asm volatile("cp.async.wait_group 1;" ::: "memory");
        __syncthreads();
        uint32_t Sa = sbase + (uint32_t)(s % NSTAGE) * STAGE_B;
        uint32_t Sw = Sa + TILE_B;

        #pragma unroll
        for (int kk = 0; kk < 2; kk++) {
            uint32_t chunk_off = (uint32_t)(kk * 2 + cc) * 16u;
            uint32_t afr[4][4], bfr[4][2];
            #pragma unroll
            for (int mf = 0; mf < 4; mf++) {
                uint32_t ad = Sa + (uint32_t)(wm0 + mf * 16 + rr) * PITCH + chunk_off;
                LDSM4_(afr[mf][0], afr[mf][1], afr[mf][2], afr[mf][3], ad);
            }
            #pragma unroll
            for (int nh = 0; nh < 2; nh++) {
                uint32_t bd = Sw + (uint32_t)(wn0 + nh * 16 + rr) * PITCH + chunk_off;
                LDSM4_(bfr[2*nh][0], bfr[2*nh+1][0], bfr[2*nh][1], bfr[2*nh+1][1], bd);
            }
            #pragma unroll
            for (int mf = 0; mf < 4; mf++)
                #pragma unroll
                for (int nf = 0; nf < 4; nf++)
                    mma_bf16_(acc[mf][nf], afr[mf], bfr[nf]);
        }

        if (s + 2 < nst) {
            uint32_t nb = sbase + (uint32_t)((s + 2) % NSTAGE) * STAGE_B;
            cp_tile_(A, lda, bm, (s + 2) * GBK, nb, tid);
            cp_tile_(W, K,   bn, (s + 2) * GBK, nb + TILE_B, tid);
        }
        asm volatile("cp.async.commit_group;" ::: "memory");
    }

    // epilogue: c0,c1 @(g, 2tg), c2,c3 @(g+8, 2tg)
    #pragma unroll
    for (int mf = 0; mf < 4; mf++) {
        int gr = bm + wm0 + mf * 16 + g;
        #pragma unroll
        for (int nf = 0; nf < 4; nf++) {
            int gc = bn + wn0 + nf * 8 + 2 * tg;
            if (gc >= NW) continue;
            float2 v01 = make_float2(acc[mf][nf][0], acc[mf][nf][1]);
            float2 v23 = make_float2(acc[mf][nf][2], acc[mf][nf][3]);
            float* p0 = C + (size_t)gr * ldc + gc;
            float* p1 = C + (size_t)(gr + 8) * ldc + gc;
            if (EPI == 2) {
                float2 o0 = *reinterpret_cast<float2*>(p0);
                float2 o1 = *reinterpret_cast<float2*>(p1);
                v01.x += o0.x; v01.y += o0.y;
                v23.x += o1.x; v23.y += o1.y;
            }
            *reinterpret_cast<float2*>(p0) = v01;
            *reinterpret_cast<float2*>(p1) = v23;
        }
    }
}

// ---------------- weight conversion (all layers, once per launch) ------------
#define INW_E  (4*1024*256)
#define XPW_E  (4*128*512)
#define OUTW_E (4*256*512)
__global__ void wconv_kernel(const float* __restrict__ in_w,
                             const float* __restrict__ xpw,
                             const float* __restrict__ out_w) {
    int i = blockIdx.x * 256 + threadIdx.x;
    if (i < INW_E) {
        g_inw_bf[i] = __float2bfloat16(in_w[i]);
        return;
    }
    int j = i - INW_E;
    if (j < XPW_E) {
        int layer = j >> 16;            // 128*512
        int r = (j >> 9) & 127;
        int c = j & 511;
        float v = (r < NPROJ) ? xpw[((size_t)layer * NPROJ + r) * 512 + c] : 0.f;
        g_xpw_bf[j] = __float2bfloat16(v);
        return;
    }
    int k = j - XPW_E;
    if (k < OUTW_E) g_outw_bf[k] = __float2bfloat16(out_w[k]);
}

// ---------------- stem conv (k=3, pad=1) + relu ------------------------------
__global__ void stem_kernel(const float* __restrict__ x,
                            const float* __restrict__ sw,
                            const float* __restrict__ sb) {
    int t = blockIdx.x;
    int m = threadIdx.x;
    int b = t / LL, l = t % LL;
    __shared__ float xs[3][3];
    if (m < 9) {
        int c = m / 3, k = m % 3;
        int ll = l - 1 + k;
        xs[c][k] = (ll >= 0 && ll < LL) ? x[(b*3 + c)*LL + ll] : 0.f;
    }
    __syncthreads();
    float acc = sb[m];
    #pragma unroll
    for (int c = 0; c < 3; c++)
        #pragma unroll
        for (int k = 0; k < 3; k++)
            acc = fmaf(xs[c][k], sw[(m*3 + c)*3 + k], acc);
    g_h[t*DM + m] = fmaxf(acc, 0.f);
}

// ---------------- layernorm -> bf16, warp-per-token --------------------------
__device__ __forceinline__ float warp_sum_(float v) {
    #pragma unroll
    for (int o = 16; o; o >>= 1) v += __shfl_xor_sync(0xffffffffu, v, o);
    return v;
}
__global__ __launch_bounds__(256) void ln_kernel(const float* __restrict__ in,
                                                 const float* __restrict__ g,
                                                 const float* __restrict__ b) {
    int wid = threadIdx.x >> 5, lane = threadIdx.x & 31;
    int t = blockIdx.x * 8 + wid;
    const float* row = in + (size_t)t * DM + lane * 8;
    float4 v0 = *reinterpret_cast<const float4*>(row);
    float4 v1 = *reinterpret_cast<const float4*>(row + 4);
    float s = v0.x+v0.y+v0.z+v0.w + v1.x+v1.y+v1.z+v1.w;
    float mean = warp_sum_(s) * (1.f / DM);
    float d0 = v0.x-mean, d1 = v0.y-mean, d2 = v0.z-mean, d3 = v0.w-mean;
    float d4 = v1.x-mean, d5 = v1.y-mean, d6 = v1.z-mean, d7 = v1.w-mean;
    float q = d0*d0+d1*d1+d2*d2+d3*d3+d4*d4+d5*d5+d6*d6+d7*d7;
    float rstd = rsqrtf(warp_sum_(q) * (1.f / DM) + 1e-5f);
    float4 g0 = *reinterpret_cast<const float4*>(g + lane * 8);
    float4 g1 = *reinterpret_cast<const float4*>(g + lane * 8 + 4);
    float4 b0 = *reinterpret_cast<const float4*>(b + lane * 8);
    float4 b1 = *reinterpret_cast<const float4*>(b + lane * 8 + 4);
    uint4 o;
    o.x = bf2_(d0*rstd*g0.x + b0.x, d1*rstd*g0.y + b0.y);
    o.y = bf2_(d2*rstd*g0.z + b0.z, d3*rstd*g0.w + b0.w);
    o.z = bf2_(d4*rstd*g1.x + b1.x, d5*rstd*g1.y + b1.y);
    o.w = bf2_(d6*rstd*g1.z + b1.z, d7*rstd*g1.w + b1.w);
    *reinterpret_cast<uint4*>(g_xn_bf + (size_t)t * DM + lane * 8) = o;
}

// ---------------- causal depthwise conv (k=4, left pad 3) + silu -------------
__global__ void conv_silu_kernel(const float* __restrict__ cw,
                                 const float* __restrict__ cb) {
    int idx = blockIdx.x * blockDim.x + threadIdx.x;
    if (idx >= TOK*DI) return;
    int d = idx % DI;
    int t = idx / DI;
    int l = t % LL;
    float acc = cb[d];
    #pragma unroll
    for (int k = 0; k < 4; k++) {
        int ls = l - 3 + k;
        if (ls >= 0)
            acc = fmaf(g_xz[(size_t)(t - 3 + k)*(2*DI) + d], cw[d*4 + k], acc);
    }
    float r = acc * sigmoidf_(acc);
    g_u[idx] = r;
    g_u_bf[idx] = __float2bfloat16(r);
}

// ---------------- selective scan, quad-per-channel (4 states/thread) ---------
// grid (DI/32, BN), 128 threads. Each group of 4 threads owns one d:
// sub = tid&3 handles states [4sub, 4sub+4). delta-dot and y reduced via
// shfl_xor within the quad. delta = softplus(dt·dtw[d] + dtb[d]) fused.
// Fast path (A[s] = -(s+1)): per-sub powers of q = exp(-delta).
#define SCH 8
__global__ __launch_bounds__(128) void scan_kernel(const float* __restrict__ Alog,
                                                   const float* __restrict__ Dp,
                                                   const float* __restrict__ dtw,
                                                   const float* __restrict__ dtb) {
    int b = blockIdx.y;
    int tid = threadIdx.x;
    int sub = tid & 3;
    int dl  = tid >> 2;                  // 0..31
    int d = blockIdx.x * 32 + dl;
    int s0 = sub * 4;

    float4 av = *reinterpret_cast<const float4*>(Alog + d*DS + s0);
    float A0 = -__expf(av.x), A1 = -__expf(av.y);
    float A2 = -__expf(av.z), A3 = -__expf(av.w);
    bool fast = fabsf(A0 + (float)(s0+1)) < 1e-3f &&
                fabsf(A1 + (float)(s0+2)) < 1e-3f &&
                fabsf(A2 + (float)(s0+3)) < 1e-3f &&
                fabsf(A3 + (float)(s0+4)) < 1e-3f;
    fast = __all_sync(0xffffffffu, fast);
    float4 wv = *reinterpret_cast<const float4*>(dtw + d*DTR + s0);
    float bdt = dtb[d];
    float Dd = Dp[d];
    float h0 = 0.f, h1 = 0.f, h2 = 0.f, h3 = 0.f;

    __shared__ float sD[SCH][DTR];
    __shared__ float sB[SCH][DS];
    __shared__ float sC[SCH][DS];
    int t0 = b * LL;

    for (int l0 = 0; l0 < LL; l0 += SCH) {
        // cooperative load of proj rows: SCH*48 = 384 floats / 128 threads
        #pragma unroll
        for (int r = 0; r < 3; r++) {
            int i = tid + r*128;
            int step = i / NPROJ;
            int j = i - step * NPROJ;
            float val = g_proj[(size_t)(t0 + l0 + step)*NPROJ + j];
            if (j < DTR)         sD[step][j] = val;
            else if (j < DTR+DS) sB[step][j - DTR] = val;
            else                 sC[step][j - DTR - DS] = val;
        }
        __syncthreads();

        float uc[SCH], zc[SCH], dlt[SCH];
        #pragma unroll
        for (int i = 0; i < SCH; i++) {
            size_t t = (size_t)(t0 + l0 + i);
            uc[i] = g_u[t*DI + d];
            zc[i] = g_xz[t*2*DI + DI + d];
        }
        // precompute deltas for the chunk (exposes shfl latency as ILP)
        #pragma unroll
        for (int i = 0; i < SCH; i++) {
            float part = sD[i][s0]*wv.x + sD[i][s0+1]*wv.y
                       + sD[i][s0+2]*wv.z + sD[i][s0+3]*wv.w;
            part += __shfl_xor_sync(0xffffffffu, part, 1);
            part += __shfl_xor_sync(0xffffffffu, part, 2);
            dlt[i] = softplusf_(part + bdt);
        }
        #pragma unroll
        for (int i = 0; i < SCH; i++) {
            float dl_ = dlt[i], uu = uc[i];
            float du = dl_ * uu;
            float e0, e1, e2, e3;
            if (fast) {
                float q = __expf(-dl_);
                float q2 = q*q, q4 = q2*q2, q8 = q4*q4;
                float qp = ((sub & 1) ? q4 : 1.f) * ((sub & 2) ? q8 : 1.f);
                e0 = qp*q; e1 = e0*q; e2 = e1*q; e3 = e2*q;
            } else {
                e0 = __expf(dl_*A0); e1 = __expf(dl_*A1);
                e2 = __expf(dl_*A2); e3 = __expf(dl_*A3);
            }
            h0 = fmaf(h0, e0, du * sB[i][s0]);
            h1 = fmaf(h1, e1, du * sB[i][s0+1]);
            h2 = fmaf(h2, e2, du * sB[i][s0+2]);
            h3 = fmaf(h3, e3, du * sB[i][s0+3]);
            float y = h0*sC[i][s0] + h1*sC[i][s0+1]
                    + h2*sC[i][s0+2] + h3*sC[i][s0+3];
            y += __shfl_xor_sync(0xffffffffu, y, 1);
            y += __shfl_xor_sync(0xffffffffu, y, 2);
            if (sub == 0) {
                float yy = fmaf(uu, Dd, y);
                float zz = zc[i];
                yy *= zz * sigmoidf_(zz);
                g_y_bf[(size_t)(t0 + l0 + i)*DI + d] = __float2bfloat16(yy);
            }
        }
        __syncthreads();
    }
}

// ---------------- final LN + head projection + sigmoid (warp/token) ----------
__global__ __launch_bounds__(256) void head_kernel(const float* __restrict__ g,
                                                   const float* __restrict__ b,
                                                   const float* __restrict__ hw,
                                                   const float* __restrict__ hb,
                                                   float* __restrict__ out) {
    int wid = threadIdx.x >> 5, lane = threadIdx.x & 31;
    int t = blockIdx.x * 8 + wid;
    const float* row = g_h + (size_t)t * DM + lane * 8;
    float4 v0 = *reinterpret_cast<const float4*>(row);
    float4 v1 = *reinterpret_cast<const float4*>(row + 4);
    float s = v0.x+v0.y+v0.z+v0.w + v1.x+v1.y+v1.z+v1.w;
    float mean = warp_sum_(s) * (1.f / DM);
    float d0 = v0.x-mean, d1 = v0.y-mean, d2 = v0.z-mean, d3 = v0.w-mean;
    float d4 = v1.x-mean, d5 = v1.y-mean, d6 = v1.z-mean, d7 = v1.w-mean;
    float q = d0*d0+d1*d1+d2*d2+d3*d3+d4*d4+d5*d5+d6*d6+d7*d7;
    float rstd = rsqrtf(warp_sum_(q) * (1.f / DM) + 1e-5f);
    float4 g0 = *reinterpret_cast<const float4*>(g + lane * 8);
    float4 g1 = *reinterpret_cast<const float4*>(g + lane * 8 + 4);
    float4 b0 = *reinterpret_cast<const float4*>(b + lane * 8);
    float4 b1 = *reinterpret_cast<const float4*>(b + lane * 8 + 4);
    float4 w0 = *reinterpret_cast<const float4*>(hw + lane * 8);
    float4 w1 = *reinterpret_cast<const float4*>(hw + lane * 8 + 4);
    float dot =
        (d0*rstd*g0.x + b0.x)*w0.x + (d1*rstd*g0.y + b0.y)*w0.y +
        (d2*rstd*g0.z + b0.z)*w0.z + (d3*rstd*g0.w + b0.w)*w0.w +
        (d4*rstd*g1.x + b1.x)*w1.x + (d5*rstd*g1.y + b1.y)*w1.y +
        (d6*rstd*g1.z + b1.z)*w1.z + (d7*rstd*g1.w + b1.w)*w1.w;
    float tot = warp_sum_(dot);
    if (lane == 0) out[t] = sigmoidf_(tot + hb[0]);
}

// ---------------- host launcher ----------------------------------------------
extern "C" void kernel_launch(void* const* d_in, const int* in_sizes, int n_in,
                              void* d_out, int out_size) {
    const float* x       = (const float*)d_in[0];
    const float* stem_w  = (const float*)d_in[1];
    const float* stem_b  = (const float*)d_in[2];
    const float* norm_g  = (const float*)d_in[3];
    const float* norm_b  = (const float*)d_in[4];
    const float* in_w    = (const float*)d_in[5];
    const float* conv_w  = (const float*)d_in[6];
    const float* conv_b  = (const float*)d_in[7];
    const float* xpw     = (const float*)d_in[8];
    const float* dtw     = (const float*)d_in[9];
    const float* dtb     = (const float*)d_in[10];
    const float* A_log   = (const float*)d_in[11];
    const float* Dp      = (const float*)d_in[12];
    const float* out_w   = (const float*)d_in[13];
    const float* fn_g    = (const float*)d_in[14];
    const float* fn_b    = (const float*)d_in[15];
    const float* head_w  = (const float*)d_in[16];
    const float* head_b  = (const float*)d_in[17];
    float* out = (float*)d_out;

    float *p_h, *p_xz, *p_u, *p_proj;
    __nv_bfloat16 *p_xn_bf, *p_u_bf, *p_y_bf, *p_inw, *p_xpw, *p_outw;
    cudaGetSymbolAddress((void**)&p_h,     g_h);
    cudaGetSymbolAddress((void**)&p_xz,    g_xz);
    cudaGetSymbolAddress((void**)&p_u,     g_u);
    cudaGetSymbolAddress((void**)&p_proj,  g_proj);
    cudaGetSymbolAddress((void**)&p_xn_bf, g_xn_bf);
    cudaGetSymbolAddress((void**)&p_u_bf,  g_u_bf);
    cudaGetSymbolAddress((void**)&p_y_bf,  g_y_bf);
    cudaGetSymbolAddress((void**)&p_inw,   g_inw_bf);
    cudaGetSymbolAddress((void**)&p_xpw,   g_xpw_bf);
    cudaGetSymbolAddress((void**)&p_outw,  g_outw_bf);

    cudaFuncSetAttribute(mma_gemm_kernel<0>,
                         cudaFuncAttributeMaxDynamicSharedMemorySize, GEMM_SMEM);
    cudaFuncSetAttribute(mma_gemm_kernel<2>,
                         cudaFuncAttributeMaxDynamicSharedMemorySize, GEMM_SMEM);

    wconv_kernel<<<(INW_E + XPW_E + OUTW_E)/256, 256>>>(in_w, xpw, out_w);
    stem_kernel<<<TOK, 256>>>(x, stem_w, stem_b);

    for (int i = 0; i < 4; i++) {
        ln_kernel<<<TOK/8, 256>>>(p_h, norm_g + i*DM, norm_b + i*DM);

        // in_proj (bf16 mma + cp.async): [TOK,1024] = xn @ W^T
        {
            dim3 grid((2*DI)/GBN, TOK/GBM);
            mma_gemm_kernel<0><<<grid, 256, GEMM_SMEM>>>(
                p_xn_bf, DM, p_inw + (size_t)i*1024*256, p_xz, 2*DI, DM, 2*DI);
        }

        conv_silu_kernel<<<(TOK*DI + 255)/256, 256>>>(conv_w + (size_t)i*DI*4,
                                                      conv_b + (size_t)i*DI);

        // x_proj: [TOK,48] = u @ xw^T (W padded to 128 rows)
        {
            dim3 grid(1, TOK/GBM);
            mma_gemm_kernel<0><<<grid, 256, GEMM_SMEM>>>(
                p_u_bf, DI, p_xpw + (size_t)i*128*512, p_proj, NPROJ, DI, NPROJ);
        }

        // scan + fused delta + gate (quad-per-channel)
        {
            dim3 grid(DI/32, BN);
            scan_kernel<<<grid, 128>>>(A_log + (size_t)i*DI*DS, Dp + (size_t)i*DI,
                                       dtw + (size_t)i*DI*DTR, dtb + (size_t)i*DI);
        }

        // out proj + residual: h += y @ ow^T
        {
            dim3 grid(DM/GBN, TOK/GBM);
            mma_gemm_kernel<2><<<grid, 256, GEMM_SMEM>>>(
                p_y_bf, DI, p_outw + (size_t)i*256*512, p_h, DM, DI, DM);
        }
    }

    head_kernel<<<TOK/8, 256>>>(fn_g, fn_b, head_w, head_b, out);
    (void)in_sizes; (void)n_in; (void)out_size;
}